// round 7
// baseline (speedup 1.0000x reference)
#include <cuda_runtime.h>
#include <math.h>

// Problem constants
#define BB   4
#define NTOK 4096
#define DM   1024
#define DH   256
#define SM_  256
#define HIDN 32
#define MTOT (BB*NTOK)   // 16384

// ---------------- scratch ----------------
__device__ float g_ctx[BB*DM];
__device__ float g_gamma[BB];
__device__ float g_p[MTOT];
__device__ float g_ppc[(size_t)MTOT*512];     // [pr | pi]
__device__ float g_Bcat[512*512];             // [[Mr^T, Mi^T],[Mi^T, -Mr^T]]
__device__ float g_reim[(size_t)MTOT*512];    // [re | im]
__device__ float g_attn[(size_t)MTOT*256];
__device__ float g_av[(size_t)MTOT*1024];
__device__ float g_ao[(size_t)MTOT*1024];
__device__ float g_h1[(size_t)MTOT*1024];
__device__ float g_ffi[(size_t)MTOT*4096];
__device__ float g_ff2[(size_t)MTOT*1024];

__device__ __forceinline__ float warp_sum(float v) {
#pragma unroll
    for (int o = 16; o > 0; o >>= 1) v += __shfl_xor_sync(0xffffffffu, v, o);
    return v;
}
__device__ __forceinline__ float gelu_exact(float x) {
    return 0.5f * x * (1.0f + erff(x * 0.70710678118654752440f));
}

// ---------------- ctx = mean over N ----------------
__global__ void ctx_kernel(const float* __restrict__ h) {
    int d = blockIdx.x * blockDim.x + threadIdx.x;
    int b = blockIdx.y;
    const float* hp = h + ((size_t)b * NTOK) * DM + d;
    float s = 0.f;
    for (int n = 0; n < NTOK; n++) s += hp[(size_t)n * DM];
    g_ctx[b * DM + d] = s * (1.0f / NTOK);
}

// ---------------- gamma gate ----------------
__global__ void gamma_kernel(const float* __restrict__ gw1, const float* __restrict__ gb1,
                             const float* __restrict__ gg,  const float* __restrict__ gbeta,
                             const float* __restrict__ gw2, const float* __restrict__ gb2) {
    int b = blockIdx.x;
    int j = threadIdx.x;
    const float* c = g_ctx + b * DM;
    float t = gb1[j];
    for (int k = 0; k < DM; k++) t += c[k] * gw1[k * HIDN + j];
    float mu  = warp_sum(t) * (1.f / 32.f);
    float dv  = t - mu;
    float var = warp_sum(dv * dv) * (1.f / 32.f);
    float tn  = dv * rsqrtf(var + 1e-5f) * gg[j] + gbeta[j];
    float s   = tn / (1.f + expf(-tn));
    float z   = warp_sum(s * gw2[j]);
    if (j == 0) g_gamma[b] = 1.f / (1.f + expf(-(z + gb2[0])));
}

// ---------------- normalize memory + build Bcat ----------------
__global__ void mem_kernel(const float* __restrict__ m_real, const float* __restrict__ m_imag) {
    int s = blockIdx.x;
    int k = threadIdx.x;
    float mr = m_real[s * DH + k];
    float mi = m_imag[s * DH + k];
    __shared__ float red[256];
    red[k] = mr * mr + mi * mi;
    __syncthreads();
    for (int o = 128; o > 0; o >>= 1) { if (k < o) red[k] += red[k + o]; __syncthreads(); }
    __shared__ float sc;
    if (k == 0) sc = 1.f / fmaxf(sqrtf(red[0]), 1e-12f);
    __syncthreads();
    float a = mr * sc, b = mi * sc;
    g_Bcat[k * 512 + s]               = a;
    g_Bcat[(256 + k) * 512 + s]       = b;
    g_Bcat[k * 512 + 256 + s]         = b;
    g_Bcat[(256 + k) * 512 + 256 + s] = -a;
}

// ---------------- per-token: normalize psi, uncertainty gate, p ----------------
__global__ void rownorm_gate_kernel(const float* __restrict__ h,
    const float* __restrict__ uw1, const float* __restrict__ ub1,
    const float* __restrict__ ug,  const float* __restrict__ ubeta,
    const float* __restrict__ uw2, const float* __restrict__ ub2) {
    int m = blockIdx.x;
    int tid = threadIdx.x;
    float* row = g_ppc + (size_t)m * 512;
    float v0 = row[tid], v1 = row[256 + tid];
    __shared__ float red[256];
    red[tid] = v0 * v0 + v1 * v1;
    __syncthreads();
    for (int o = 128; o > 0; o >>= 1) { if (tid < o) red[tid] += red[tid + o]; __syncthreads(); }
    __shared__ float sc;
    if (tid == 0) sc = 1.f / fmaxf(sqrtf(red[0]), 1e-12f);
    __syncthreads();
    row[tid] = v0 * sc;
    row[256 + tid] = v1 * sc;

    int j = tid & 31, part = tid >> 5;
    const float* hr = h + (size_t)m * DM;
    float partial = 0.f;
    int k0 = part * 128;
    for (int k = k0; k < k0 + 128; k++) partial += hr[k] * uw1[k * HIDN + j];
    __shared__ float gred[8][32];
    gred[part][j] = partial;
    __syncthreads();
    if (tid < 32) {
        float t = ub1[tid];
#pragma unroll
        for (int q = 0; q < 8; q++) t += gred[q][tid];
        float mu  = warp_sum(t) * (1.f / 32.f);
        float dv  = t - mu;
        float var = warp_sum(dv * dv) * (1.f / 32.f);
        float tn  = dv * rsqrtf(var + 1e-5f) * ug[tid] + ubeta[tid];
        float s   = tn / (1.f + expf(-tn));
        float z   = warp_sum(s * uw2[tid]);
        if (tid == 0) {
            float pin = 0.95f / (1.f + expf(-(z + ub2[0])));
            g_p[m] = pin * (1.f - g_gamma[m >> 12]);
        }
    }
}

// ---------------- attention row normalize ----------------
__global__ void attn_kernel() {
    int m = blockIdx.x;
    int s = threadIdx.x;
    float re = g_reim[(size_t)m * 512 + s];
    float im = g_reim[(size_t)m * 512 + 256 + s];
    float pm = g_p[m];
    float raw = (1.f - pm) * (re * re + im * im) + pm * (1.f / 256.f);
    __shared__ float red[256];
    red[s] = raw;
    __syncthreads();
    for (int o = 128; o > 0; o >>= 1) { if (s < o) red[s] += red[s + o]; __syncthreads(); }
    g_attn[(size_t)m * 256 + s] = raw / (red[0] + 1e-8f);
}

// ---------------- LayerNorm(x + y) ----------------
__global__ void ln_kernel(const float* __restrict__ x, const float* __restrict__ y,
                          const float* __restrict__ g, const float* __restrict__ bta,
                          float* __restrict__ out) {
    int m = blockIdx.x;
    int tid = threadIdx.x;
    size_t base = (size_t)m * DM;
    float v[4];
    float s1 = 0.f, s2 = 0.f;
#pragma unroll
    for (int i = 0; i < 4; i++) {
        int d = tid + 256 * i;
        v[i] = x[base + d] + y[base + d];
        s1 += v[i];
        s2 += v[i] * v[i];
    }
    __shared__ float r1[256], r2[256];
    r1[tid] = s1; r2[tid] = s2;
    __syncthreads();
    for (int o = 128; o > 0; o >>= 1) {
        if (tid < o) { r1[tid] += r1[tid + o]; r2[tid] += r2[tid + o]; }
        __syncthreads();
    }
    float mu  = r1[0] * (1.f / 1024.f);
    float var = r2[0] * (1.f / 1024.f) - mu * mu;
    float inv = rsqrtf(var + 1e-5f);
#pragma unroll
    for (int i = 0; i < 4; i++) {
        int d = tid + 256 * i;
        out[base + d] = (v[i] - mu) * inv * g[d] + bta[d];
    }
}

// ================= tf32 tensor-core GEMM (256 threads) =================
// C(MxN) = A(MxK, row-major) @ B(KxN, row-major) [+bias][+gelu]
// CTA tile 128x128x16, 8 warps, warp tile 32x64 (2 m-subtiles x 8 n-subtiles).
#define TBM 128
#define TBN 128
#define TBK 16
#define AST 20     // As row stride: frag bank = (20g + tg) mod 32, all distinct
#define BST 136    // Bs row stride: frag bank = (8tg + g) mod 32, all distinct

__device__ __forceinline__ void cp_async16(void* sdst, const void* gsrc) {
    unsigned s = (unsigned)__cvta_generic_to_shared(sdst);
    asm volatile("cp.async.cg.shared.global [%0], [%1], 16;\n" :: "r"(s), "l"(gsrc));
}
__device__ __forceinline__ void cp_commit() { asm volatile("cp.async.commit_group;\n"); }
__device__ __forceinline__ void cp_wait1()  { asm volatile("cp.async.wait_group 1;\n"); }
__device__ __forceinline__ void cp_wait0()  { asm volatile("cp.async.wait_group 0;\n"); }

__device__ __forceinline__ void mma_tf32(float* d, const unsigned* a, const unsigned* b) {
    asm volatile(
        "mma.sync.aligned.m16n8k8.row.col.f32.tf32.tf32.f32 "
        "{%0,%1,%2,%3}, {%4,%5,%6,%7}, {%8,%9}, {%0,%1,%2,%3};"
        : "+f"(d[0]), "+f"(d[1]), "+f"(d[2]), "+f"(d[3])
        : "r"(a[0]), "r"(a[1]), "r"(a[2]), "r"(a[3]), "r"(b[0]), "r"(b[1]));
}

template <int EPI>  // 0: none, 1: +bias, 2: +bias+gelu
__global__ __launch_bounds__(256, 2) void tgemm_kernel(
    const float* __restrict__ A, const float* __restrict__ B,
    const float* __restrict__ bias, float* __restrict__ C,
    int M, int N, int K, int lda, int ldb, int ldc) {
    __shared__ float As[2][TBM * AST];
    __shared__ float Bs[2][TBK * BST];

    int tid  = threadIdx.x;
    int warp = tid >> 5, lane = tid & 31;
    int g = lane >> 2, tg = lane & 3;
    int wm = warp >> 1, wn = warp & 1;   // wm 0..3 (32 rows each), wn 0..1 (64 cols each)
    int row0 = blockIdx.y * TBM, col0 = blockIdx.x * TBN;

    // load mapping: 512 float4 chunks per matrix, 2 per thread
    int am[2], ak[2], bk[2], bn[2];
#pragma unroll
    for (int i = 0; i < 2; i++) {
        int c = tid + i * 256;
        am[i] = c >> 2;  ak[i] = (c & 3) * 4;
        bk[i] = c >> 5;  bn[i] = (c & 31) * 4;
    }

    float acc[2][8][4];
#pragma unroll
    for (int mi = 0; mi < 2; mi++)
#pragma unroll
        for (int ni = 0; ni < 8; ni++)
#pragma unroll
            for (int r = 0; r < 4; r++) acc[mi][ni][r] = 0.f;

    int T = K / TBK;

    // prologue: stage 0
    {
#pragma unroll
        for (int i = 0; i < 2; i++)
            cp_async16(&As[0][am[i] * AST + ak[i]],
                       A + (size_t)(row0 + am[i]) * lda + ak[i]);
#pragma unroll
        for (int i = 0; i < 2; i++)
            cp_async16(&Bs[0][bk[i] * BST + bn[i]],
                       B + (size_t)bk[i] * ldb + col0 + bn[i]);
        cp_commit();
    }

    for (int t = 0; t < T; t++) {
        if (t + 1 < T) {
            int s = (t + 1) & 1, k0 = (t + 1) * TBK;
#pragma unroll
            for (int i = 0; i < 2; i++)
                cp_async16(&As[s][am[i] * AST + ak[i]],
                           A + (size_t)(row0 + am[i]) * lda + k0 + ak[i]);
#pragma unroll
            for (int i = 0; i < 2; i++)
                cp_async16(&Bs[s][bk[i] * BST + bn[i]],
                           B + (size_t)(k0 + bk[i]) * ldb + col0 + bn[i]);
            cp_commit();
            cp_wait1();
        } else {
            cp_wait0();
        }
        __syncthreads();

        const unsigned* as = (const unsigned*)As[t & 1];
        const unsigned* bs = (const unsigned*)Bs[t & 1];
#pragma unroll
        for (int kk = 0; kk < TBK; kk += 8) {
            unsigned af[2][4], bf[8][2];
#pragma unroll
            for (int mi = 0; mi < 2; mi++) {
                int r = wm * 32 + mi * 16 + g;
                int c = kk + tg;
                af[mi][0] = as[r * AST + c];
                af[mi][1] = as[(r + 8) * AST + c];
                af[mi][2] = as[r * AST + c + 4];
                af[mi][3] = as[(r + 8) * AST + c + 4];
            }
#pragma unroll
            for (int ni = 0; ni < 8; ni++) {
                int c = wn * 64 + ni * 8 + g;
                bf[ni][0] = bs[(kk + tg) * BST + c];
                bf[ni][1] = bs[(kk + tg + 4) * BST + c];
            }
#pragma unroll
            for (int mi = 0; mi < 2; mi++)
#pragma unroll
                for (int ni = 0; ni < 8; ni++)
                    mma_tf32(acc[mi][ni], af[mi], bf[ni]);
        }
        __syncthreads();
    }

    // epilogue
#pragma unroll
    for (int mi = 0; mi < 2; mi++) {
        int r0 = row0 + wm * 32 + mi * 16 + g;
        int r1 = r0 + 8;
#pragma unroll
        for (int ni = 0; ni < 8; ni++) {
            int c = col0 + wn * 64 + ni * 8 + 2 * tg;
            float b0 = 0.f, b1 = 0.f;
            if (EPI > 0) { b0 = bias[c]; b1 = bias[c + 1]; }
            float v0 = acc[mi][ni][0] + b0;
            float v1 = acc[mi][ni][1] + b1;
            float v2 = acc[mi][ni][2] + b0;
            float v3 = acc[mi][ni][3] + b1;
            if (EPI == 2) {
                v0 = gelu_exact(v0); v1 = gelu_exact(v1);
                v2 = gelu_exact(v2); v3 = gelu_exact(v3);
            }
            *(float2*)(C + (size_t)r0 * ldc + c) = make_float2(v0, v1);
            *(float2*)(C + (size_t)r1 * ldc + c) = make_float2(v2, v3);
        }
    }
}

// ---------------- launch ----------------
extern "C" void kernel_launch(void* const* d_in, const int* in_sizes, int n_in,
                              void* d_out, int out_size) {
    const float* h      = (const float*)d_in[0];
    const float* Wr     = (const float*)d_in[1];
    const float* br     = (const float*)d_in[2];
    const float* Wi     = (const float*)d_in[3];
    const float* bi     = (const float*)d_in[4];
    const float* uw1    = (const float*)d_in[5];
    const float* ub1    = (const float*)d_in[6];
    const float* ug     = (const float*)d_in[7];
    const float* ubeta  = (const float*)d_in[8];
    const float* uw2    = (const float*)d_in[9];
    const float* ub2    = (const float*)d_in[10];
    const float* gw1    = (const float*)d_in[11];
    const float* gb1    = (const float*)d_in[12];
    const float* gg     = (const float*)d_in[13];
    const float* gbeta  = (const float*)d_in[14];
    const float* gw2    = (const float*)d_in[15];
    const float* gb2    = (const float*)d_in[16];
    const float* m_real = (const float*)d_in[17];
    const float* m_imag = (const float*)d_in[18];
    const float* values = (const float*)d_in[19];
    const float* ow     = (const float*)d_in[20];
    const float* ob     = (const float*)d_in[21];
    const float* n1g    = (const float*)d_in[22];
    const float* n1b    = (const float*)d_in[23];
    const float* n2g    = (const float*)d_in[24];
    const float* n2b    = (const float*)d_in[25];
    const float* fw1    = (const float*)d_in[26];
    const float* fb1    = (const float*)d_in[27];
    const float* fw2    = (const float*)d_in[28];
    const float* fb2    = (const float*)d_in[29];
    float* out = (float*)d_out;

    float *ppc, *Bcat, *reim, *attn, *av, *ao, *h1, *ffi, *ff2;
    cudaGetSymbolAddress((void**)&ppc,  g_ppc);
    cudaGetSymbolAddress((void**)&Bcat, g_Bcat);
    cudaGetSymbolAddress((void**)&reim, g_reim);
    cudaGetSymbolAddress((void**)&attn, g_attn);
    cudaGetSymbolAddress((void**)&av,   g_av);
    cudaGetSymbolAddress((void**)&ao,   g_ao);
    cudaGetSymbolAddress((void**)&h1,   g_h1);
    cudaGetSymbolAddress((void**)&ffi,  g_ffi);
    cudaGetSymbolAddress((void**)&ff2,  g_ff2);

    ctx_kernel<<<dim3(DM / 256, BB), 256>>>(h);
    gamma_kernel<<<BB, 32>>>(gw1, gb1, gg, gbeta, gw2, gb2);
    mem_kernel<<<SM_, 256>>>(m_real, m_imag);

    // encoder: pr | pi -> ppc (M,512)
    tgemm_kernel<1><<<dim3(2, MTOT / TBM), 256>>>(h, Wr, br, ppc,       MTOT, 256,  1024, 1024, 256,  512);
    tgemm_kernel<1><<<dim3(2, MTOT / TBM), 256>>>(h, Wi, bi, ppc + 256, MTOT, 256,  1024, 1024, 256,  512);

    rownorm_gate_kernel<<<MTOT, 256>>>(h, uw1, ub1, ug, ubeta, uw2, ub2);

    // complex overlap: reim = ppc @ Bcat (M,512)
    tgemm_kernel<0><<<dim3(4, MTOT / TBM), 256>>>(ppc, Bcat, nullptr, reim, MTOT, 512,  512,  512,  512,  512);

    attn_kernel<<<MTOT, 256>>>();

    tgemm_kernel<0><<<dim3(8, MTOT / TBM), 256>>>(attn, values, nullptr, av, MTOT, 1024, 256,  256,  1024, 1024);
    tgemm_kernel<1><<<dim3(8, MTOT / TBM), 256>>>(av,   ow,     ob,      ao, MTOT, 1024, 1024, 1024, 1024, 1024);

    ln_kernel<<<MTOT, 256>>>(h, ao, n1g, n1b, h1);

    tgemm_kernel<2><<<dim3(32, MTOT / TBM), 256>>>(h1,  fw1, fb1, ffi, MTOT, 4096, 1024, 1024, 4096, 4096);
    tgemm_kernel<1><<<dim3(8,  MTOT / TBM), 256>>>(ffi, fw2, fb2, ff2, MTOT, 1024, 4096, 4096, 1024, 1024);

    ln_kernel<<<MTOT, 256>>>(h1, ff2, n2g, n2b, out);
}

// round 11
// speedup vs baseline: 1.4837x; 1.4837x over previous
#include <cuda_runtime.h>
#include <cuda_fp16.h>
#include <math.h>
#include <stdint.h>

// Problem constants
#define BB   4
#define NTOK 4096
#define DM   1024
#define DH   256
#define SM_  256
#define HIDN 32
#define MTOT (BB*NTOK)   // 16384

// ---------------- fp32 scratch ----------------
__device__ float g_ctx[BB*DM];
__device__ float g_gamma[BB];
__device__ float g_p[MTOT];
__device__ float g_ppc[(size_t)MTOT*512];     // [pr | pi] (pre/post normalize)
__device__ float g_reim[(size_t)MTOT*512];    // [re | im]
__device__ float g_ao[(size_t)MTOT*1024];
__device__ float g_h1[(size_t)MTOT*1024];
__device__ float g_ff2[(size_t)MTOT*1024];
__device__ float g_bcat_b[512];               // [br | bi]
// ---------------- fp16 GEMM operands ----------------
__device__ __half g_h_h[(size_t)MTOT*1024];
__device__ __half g_ppc_h[(size_t)MTOT*512];
__device__ __half g_attn_h[(size_t)MTOT*256];
__device__ __half g_av_h[(size_t)MTOT*1024];
__device__ __half g_h1_h[(size_t)MTOT*1024];
__device__ __half g_ffi_h[(size_t)MTOT*4096];
__device__ __half g_BcatT_h[512*512];         // [n][k]
__device__ __half g_wcat_h[512*1024];         // rows 0..255 Wr^T, 256..511 Wi^T
__device__ __half g_val_h[1024*256];
__device__ __half g_ow_h[1024*1024];
__device__ __half g_fw1_h[(size_t)4096*1024];
__device__ __half g_fw2_h[(size_t)1024*4096];

__device__ __forceinline__ float warp_sum(float v) {
#pragma unroll
    for (int o = 16; o > 0; o >>= 1) v += __shfl_xor_sync(0xffffffffu, v, o);
    return v;
}
__device__ __forceinline__ float gelu_exact(float x) {
    return 0.5f * x * (1.0f + erff(x * 0.70710678118654752440f));
}

// ---------------- fp32 -> fp16 convert ----------------
__global__ void f2h_kernel(const float* __restrict__ in, __half* __restrict__ out, size_t n) {
    size_t i = ((size_t)blockIdx.x * blockDim.x + threadIdx.x) * 4;
    if (i < n) {
        float4 v = *(const float4*)(in + i);
        __half2* o = (__half2*)(out + i);
        o[0] = __floats2half2_rn(v.x, v.y);
        o[1] = __floats2half2_rn(v.z, v.w);
    }
}

// ---------------- transpose to fp16: in[R][C] -> out[C][R] ----------------
__global__ void transpose_h_kernel(const float* __restrict__ in, __half* __restrict__ out,
                                   int R, int C) {
    __shared__ float t[32][33];
    int c0 = blockIdx.x * 32, r0 = blockIdx.y * 32;
    int x = threadIdx.x, y = threadIdx.y;  // 32x8
#pragma unroll
    for (int i = 0; i < 32; i += 8)
        t[y + i][x] = in[(size_t)(r0 + y + i) * C + c0 + x];
    __syncthreads();
#pragma unroll
    for (int i = 0; i < 32; i += 8)
        out[(size_t)(c0 + y + i) * R + r0 + x] = __float2half(t[x][y + i]);
}

// ---------------- ctx = mean over N ----------------
__global__ void ctx_kernel(const float* __restrict__ h) {
    int d = blockIdx.x * blockDim.x + threadIdx.x;
    int b = blockIdx.y;
    const float* hp = h + ((size_t)b * NTOK) * DM + d;
    float s = 0.f;
    for (int n = 0; n < NTOK; n++) s += hp[(size_t)n * DM];
    g_ctx[b * DM + d] = s * (1.0f / NTOK);
}

// ---------------- gamma gate ----------------
__global__ void gamma_kernel(const float* __restrict__ gw1, const float* __restrict__ gb1,
                             const float* __restrict__ gg,  const float* __restrict__ gbeta,
                             const float* __restrict__ gw2, const float* __restrict__ gb2) {
    int b = blockIdx.x;
    int j = threadIdx.x;
    const float* c = g_ctx + b * DM;
    float t = gb1[j];
    for (int k = 0; k < DM; k++) t += c[k] * gw1[k * HIDN + j];
    float mu  = warp_sum(t) * (1.f / 32.f);
    float dv  = t - mu;
    float var = warp_sum(dv * dv) * (1.f / 32.f);
    float tn  = dv * rsqrtf(var + 1e-5f) * gg[j] + gbeta[j];
    float s   = tn / (1.f + expf(-tn));
    float z   = warp_sum(s * gw2[j]);
    if (j == 0) g_gamma[b] = 1.f / (1.f + expf(-(z + gb2[0])));
}

// ---------------- normalize memory + build BcatT (fp16, [n][k]) ----------------
__global__ void mem_kernel(const float* __restrict__ m_real, const float* __restrict__ m_imag) {
    int s = blockIdx.x;
    int k = threadIdx.x;
    float mr = m_real[s * DH + k];
    float mi = m_imag[s * DH + k];
    __shared__ float red[256];
    red[k] = mr * mr + mi * mi;
    __syncthreads();
    for (int o = 128; o > 0; o >>= 1) { if (k < o) red[k] += red[k + o]; __syncthreads(); }
    __shared__ float sc;
    if (k == 0) sc = 1.f / fmaxf(sqrtf(red[0]), 1e-12f);
    __syncthreads();
    float a = mr * sc, b = mi * sc;
    g_BcatT_h[s * 512 + k]               = __float2half(a);    // re from pr: Mr
    g_BcatT_h[s * 512 + 256 + k]         = __float2half(b);    // re from pi: Mi
    g_BcatT_h[(256 + s) * 512 + k]       = __float2half(b);    // im from pr: Mi
    g_BcatT_h[(256 + s) * 512 + 256 + k] = __float2half(-a);   // im from pi: -Mr
}

// ---------------- bias concat ----------------
__global__ void biascat_kernel(const float* __restrict__ br, const float* __restrict__ bi) {
    int i = threadIdx.x;
    g_bcat_b[i] = (i < 256) ? br[i] : bi[i - 256];
}

// ---------------- per-token: normalize psi (fp32+fp16 out), gate, p ----------------
__global__ void rownorm_gate_kernel(const float* __restrict__ h,
    const float* __restrict__ uw1, const float* __restrict__ ub1,
    const float* __restrict__ ug,  const float* __restrict__ ubeta,
    const float* __restrict__ uw2, const float* __restrict__ ub2) {
    int m = blockIdx.x;
    int tid = threadIdx.x;
    float* row = g_ppc + (size_t)m * 512;
    __half* rowh = g_ppc_h + (size_t)m * 512;
    float v0 = row[tid], v1 = row[256 + tid];
    __shared__ float red[256];
    red[tid] = v0 * v0 + v1 * v1;
    __syncthreads();
    for (int o = 128; o > 0; o >>= 1) { if (tid < o) red[tid] += red[tid + o]; __syncthreads(); }
    __shared__ float sc;
    if (tid == 0) sc = 1.f / fmaxf(sqrtf(red[0]), 1e-12f);
    __syncthreads();
    float n0 = v0 * sc, n1 = v1 * sc;
    rowh[tid] = __float2half(n0);
    rowh[256 + tid] = __float2half(n1);

    int j = tid & 31, part = tid >> 5;
    const float* hr = h + (size_t)m * DM;
    float partial = 0.f;
    int k0 = part * 128;
    for (int k = k0; k < k0 + 128; k++) partial += hr[k] * uw1[k * HIDN + j];
    __shared__ float gred[8][32];
    gred[part][j] = partial;
    __syncthreads();
    if (tid < 32) {
        float t = ub1[tid];
#pragma unroll
        for (int q = 0; q < 8; q++) t += gred[q][tid];
        float mu  = warp_sum(t) * (1.f / 32.f);
        float dv  = t - mu;
        float var = warp_sum(dv * dv) * (1.f / 32.f);
        float tn  = dv * rsqrtf(var + 1e-5f) * ug[tid] + ubeta[tid];
        float s   = tn / (1.f + expf(-tn));
        float z   = warp_sum(s * uw2[tid]);
        if (tid == 0) {
            float pin = 0.95f / (1.f + expf(-(z + ub2[0])));
            g_p[m] = pin * (1.f - g_gamma[m >> 12]);
        }
    }
}

// ---------------- attention row normalize (fp16 out) ----------------
__global__ void attn_kernel() {
    int m = blockIdx.x;
    int s = threadIdx.x;
    float re = g_reim[(size_t)m * 512 + s];
    float im = g_reim[(size_t)m * 512 + 256 + s];
    float pm = g_p[m];
    float raw = (1.f - pm) * (re * re + im * im) + pm * (1.f / 256.f);
    __shared__ float red[256];
    red[s] = raw;
    __syncthreads();
    for (int o = 128; o > 0; o >>= 1) { if (s < o) red[s] += red[s + o]; __syncthreads(); }
    g_attn_h[(size_t)m * 256 + s] = __float2half(raw / (red[0] + 1e-8f));
}

// ---------------- LayerNorm(x + y), optional fp16 secondary output ----------------
__global__ void ln_kernel(const float* __restrict__ x, const float* __restrict__ y,
                          const float* __restrict__ g, const float* __restrict__ bta,
                          float* __restrict__ out, __half* __restrict__ outh) {
    int m = blockIdx.x;
    int tid = threadIdx.x;
    size_t base = (size_t)m * DM;
    float v[4];
    float s1 = 0.f, s2 = 0.f;
#pragma unroll
    for (int i = 0; i < 4; i++) {
        int d = tid + 256 * i;
        v[i] = x[base + d] + y[base + d];
        s1 += v[i];
        s2 += v[i] * v[i];
    }
    __shared__ float r1[256], r2[256];
    r1[tid] = s1; r2[tid] = s2;
    __syncthreads();
    for (int o = 128; o > 0; o >>= 1) {
        if (tid < o) { r1[tid] += r1[tid + o]; r2[tid] += r2[tid + o]; }
        __syncthreads();
    }
    float mu  = r1[0] * (1.f / 1024.f);
    float var = r2[0] * (1.f / 1024.f) - mu * mu;
    float inv = rsqrtf(var + 1e-5f);
#pragma unroll
    for (int i = 0; i < 4; i++) {
        int d = tid + 256 * i;
        float o = (v[i] - mu) * inv * g[d] + bta[d];
        out[base + d] = o;
        if (outh) outh[base + d] = __float2half(o);
    }
}

// ================= fp16 m16n8k16 tensor-core GEMM =================
// C[M,N] = A[M,K] @ Bt[N,K]^T (+bias, +gelu). A,Bt fp16 row-major; C fp32 or fp16.
// 128 threads, 4 warps, warp tile 64x64, CTA 128x128, TBK=32 halves,
// double-buffered cp.async. smem u32 stride 20: fragment banks (20g+tg) all distinct.
#define TBM 128
#define TBN 128
#define TBKH 32
#define STR 20

__device__ __forceinline__ void cp_async16(void* sdst, const void* gsrc) {
    unsigned s = (unsigned)__cvta_generic_to_shared(sdst);
    asm volatile("cp.async.cg.shared.global [%0], [%1], 16;\n" :: "r"(s), "l"(gsrc));
}
__device__ __forceinline__ void cp_commit() { asm volatile("cp.async.commit_group;\n"); }
__device__ __forceinline__ void cp_wait1()  { asm volatile("cp.async.wait_group 1;\n"); }
__device__ __forceinline__ void cp_wait0()  { asm volatile("cp.async.wait_group 0;\n"); }

__device__ __forceinline__ void mma_f16(float* d, const uint32_t* a, const uint32_t* b) {
    asm volatile(
        "mma.sync.aligned.m16n8k16.row.col.f32.f16.f16.f32 "
        "{%0,%1,%2,%3}, {%4,%5,%6,%7}, {%8,%9}, {%0,%1,%2,%3};"
        : "+f"(d[0]), "+f"(d[1]), "+f"(d[2]), "+f"(d[3])
        : "r"(a[0]), "r"(a[1]), "r"(a[2]), "r"(a[3]), "r"(b[0]), "r"(b[1]));
}

template <int EPI, int OUTH>  // EPI 0:none 1:+bias 2:+bias+gelu; OUTH 0:fp32 1:fp16
__global__ __launch_bounds__(128) void hgemm_kernel(
    const __half* __restrict__ A, const __half* __restrict__ Bt,
    const float* __restrict__ bias, float* __restrict__ Cf, __half* __restrict__ Ch,
    int K, int lda, int ldb, int ldc) {
    __shared__ uint32_t As[2][TBM * STR];
    __shared__ uint32_t Bs[2][TBM * STR];

    int tid  = threadIdx.x;
    int warp = tid >> 5, lane = tid & 31;
    int g = lane >> 2, tg = lane & 3;
    int wm = warp >> 1, wn = warp & 1;
    int row0 = blockIdx.y * TBM, col0 = blockIdx.x * TBN;

    const __half* Ap = A + (size_t)row0 * lda;
    const __half* Bp = Bt + (size_t)col0 * ldb;

    float acc[4][8][4];
#pragma unroll
    for (int mi = 0; mi < 4; mi++)
#pragma unroll
        for (int ni = 0; ni < 8; ni++)
#pragma unroll
            for (int r = 0; r < 4; r++) acc[mi][ni][r] = 0.f;

    int T = K / TBKH;

    // 512 16B-chunks per matrix (128 rows x 4 chunks), 4 per thread
    auto load = [&](int st, int kc) {
#pragma unroll
        for (int i = 0; i < 4; i++) {
            int c = tid + i * 128; int r = c >> 2, j = c & 3;
            cp_async16(&As[st][r * STR + j * 4], Ap + (size_t)r * lda + kc * TBKH + j * 8);
        }
#pragma unroll
        for (int i = 0; i < 4; i++) {
            int c = tid + i * 128; int r = c >> 2, j = c & 3;
            cp_async16(&Bs[st][r * STR + j * 4], Bp + (size_t)r * ldb + kc * TBKH + j * 8);
        }
        cp_commit();
    };

    load(0, 0);
    for (int t = 0; t < T; t++) {
        if (t + 1 < T) { load((t + 1) & 1, t + 1); cp_wait1(); }
        else           { cp_wait0(); }
        __syncthreads();
        const uint32_t* as = As[t & 1];
        const uint32_t* bs = Bs[t & 1];
#pragma unroll
        for (int s = 0; s < 2; s++) {          // two k16 steps per tile
            int s8 = s * 8;
            uint32_t af[4][4], bf[8][2];
#pragma unroll
            for (int mi = 0; mi < 4; mi++) {
                int r = wm * 64 + mi * 16 + g;
                af[mi][0] = as[r * STR + s8 + tg];
                af[mi][1] = as[(r + 8) * STR + s8 + tg];
                af[mi][2] = as[r * STR + s8 + tg + 4];
                af[mi][3] = as[(r + 8) * STR + s8 + tg + 4];
            }
#pragma unroll
            for (int ni = 0; ni < 8; ni++) {
                int n = wn * 64 + ni * 8 + g;
                bf[ni][0] = bs[n * STR + s8 + tg];
                bf[ni][1] = bs[n * STR + s8 + tg + 4];
            }
#pragma unroll
            for (int mi = 0; mi < 4; mi++)
#pragma unroll
                for (int ni = 0; ni < 8; ni++)
                    mma_f16(acc[mi][ni], af[mi], bf[ni]);
        }
        __syncthreads();
    }

    // epilogue
#pragma unroll
    for (int mi = 0; mi < 4; mi++) {
        int r0 = row0 + wm * 64 + mi * 16 + g;
        int r1 = r0 + 8;
#pragma unroll
        for (int ni = 0; ni < 8; ni++) {
            int c = col0 + wn * 64 + ni * 8 + 2 * tg;
            float b0 = 0.f, b1 = 0.f;
            if (EPI > 0) { b0 = bias[c]; b1 = bias[c + 1]; }
            float v0 = acc[mi][ni][0] + b0;
            float v1 = acc[mi][ni][1] + b1;
            float v2 = acc[mi][ni][2] + b0;
            float v3 = acc[mi][ni][3] + b1;
            if (EPI == 2) {
                v0 = gelu_exact(v0); v1 = gelu_exact(v1);
                v2 = gelu_exact(v2); v3 = gelu_exact(v3);
            }
            if (OUTH) {
                *(__half2*)(Ch + (size_t)r0 * ldc + c) = __floats2half2_rn(v0, v1);
                *(__half2*)(Ch + (size_t)r1 * ldc + c) = __floats2half2_rn(v2, v3);
            } else {
                *(float2*)(Cf + (size_t)r0 * ldc + c) = make_float2(v0, v1);
                *(float2*)(Cf + (size_t)r1 * ldc + c) = make_float2(v2, v3);
            }
        }
    }
}

// ---------------- launch ----------------
extern "C" void kernel_launch(void* const* d_in, const int* in_sizes, int n_in,
                              void* d_out, int out_size) {
    const float* h      = (const float*)d_in[0];
    const float* Wr     = (const float*)d_in[1];
    const float* br     = (const float*)d_in[2];
    const float* Wi     = (const float*)d_in[3];
    const float* bi     = (const float*)d_in[4];
    const float* uw1    = (const float*)d_in[5];
    const float* ub1    = (const float*)d_in[6];
    const float* ug     = (const float*)d_in[7];
    const float* ubeta  = (const float*)d_in[8];
    const float* uw2    = (const float*)d_in[9];
    const float* ub2    = (const float*)d_in[10];
    const float* gw1    = (const float*)d_in[11];
    const float* gb1    = (const float*)d_in[12];
    const float* gg     = (const float*)d_in[13];
    const float* gbeta  = (const float*)d_in[14];
    const float* gw2    = (const float*)d_in[15];
    const float* gb2    = (const float*)d_in[16];
    const float* m_real = (const float*)d_in[17];
    const float* m_imag = (const float*)d_in[18];
    const float* values = (const float*)d_in[19];
    const float* ow     = (const float*)d_in[20];
    const float* ob     = (const float*)d_in[21];
    const float* n1g    = (const float*)d_in[22];
    const float* n1b    = (const float*)d_in[23];
    const float* n2g    = (const float*)d_in[24];
    const float* n2b    = (const float*)d_in[25];
    const float* fw1    = (const float*)d_in[26];
    const float* fb1    = (const float*)d_in[27];
    const float* fw2    = (const float*)d_in[28];
    const float* fb2    = (const float*)d_in[29];
    float* out = (float*)d_out;

    float *ppc, *reim, *ao, *h1, *ff2, *bcat_b;
    __half *h_h, *ppc_h, *attn_h, *av_h, *h1_h, *ffi_h;
    __half *BcatT_h, *wcat_h, *val_h, *ow_h, *fw1_h, *fw2_h;
    cudaGetSymbolAddress((void**)&ppc,     g_ppc);
    cudaGetSymbolAddress((void**)&reim,    g_reim);
    cudaGetSymbolAddress((void**)&ao,      g_ao);
    cudaGetSymbolAddress((void**)&h1,      g_h1);
    cudaGetSymbolAddress((void**)&ff2,     g_ff2);
    cudaGetSymbolAddress((void**)&bcat_b,  g_bcat_b);
    cudaGetSymbolAddress((void**)&h_h,     g_h_h);
    cudaGetSymbolAddress((void**)&ppc_h,   g_ppc_h);
    cudaGetSymbolAddress((void**)&attn_h,  g_attn_h);
    cudaGetSymbolAddress((void**)&av_h,    g_av_h);
    cudaGetSymbolAddress((void**)&h1_h,    g_h1_h);
    cudaGetSymbolAddress((void**)&ffi_h,   g_ffi_h);
    cudaGetSymbolAddress((void**)&BcatT_h, g_BcatT_h);
    cudaGetSymbolAddress((void**)&wcat_h,  g_wcat_h);
    cudaGetSymbolAddress((void**)&val_h,   g_val_h);
    cudaGetSymbolAddress((void**)&ow_h,    g_ow_h);
    cudaGetSymbolAddress((void**)&fw1_h,   g_fw1_h);
    cudaGetSymbolAddress((void**)&fw2_h,   g_fw2_h);

    dim3 tb(32, 8);
    // weight transposes (fp16 out): in[R][C] -> out[C][R]
    transpose_h_kernel<<<dim3(256/32, 1024/32), tb>>>(Wr, wcat_h,            1024, 256);
    transpose_h_kernel<<<dim3(256/32, 1024/32), tb>>>(Wi, wcat_h + 256*1024, 1024, 256);
    transpose_h_kernel<<<dim3(1024/32, 256/32), tb>>>(values, val_h,         256, 1024);
    transpose_h_kernel<<<dim3(1024/32, 1024/32), tb>>>(ow, ow_h,             1024, 1024);
    transpose_h_kernel<<<dim3(4096/32, 1024/32), tb>>>(fw1, fw1_h,           1024, 4096);
    transpose_h_kernel<<<dim3(1024/32, 4096/32), tb>>>(fw2, fw2_h,           4096, 1024);
    biascat_kernel<<<1, 512>>>(br, bi);

    // convert h to fp16
    f2h_kernel<<<((size_t)MTOT*1024/4 + 255)/256, 256>>>(h, h_h, (size_t)MTOT*1024);

    ctx_kernel<<<dim3(DM / 256, BB), 256>>>(h);
    gamma_kernel<<<BB, 32>>>(gw1, gb1, gg, gbeta, gw2, gb2);
    mem_kernel<<<SM_, 256>>>(m_real, m_imag);

    // encoder (fused Wr|Wi): ppc[M,512] fp32 = h_h @ wcat_h^T + bcat
    hgemm_kernel<1,0><<<dim3(512/TBN, MTOT/TBM), 128>>>(h_h, wcat_h, bcat_b, ppc, nullptr, 1024, 1024, 1024, 512);

    rownorm_gate_kernel<<<MTOT, 256>>>(h, uw1, ub1, ug, ubeta, uw2, ub2);

    // overlap: reim fp32 = ppc_h @ BcatT_h^T
    hgemm_kernel<0,0><<<dim3(512/TBN, MTOT/TBM), 128>>>(ppc_h, BcatT_h, nullptr, reim, nullptr, 512, 512, 512, 512);

    attn_kernel<<<MTOT, 256>>>();

    // attn @ values -> av (fp16 only)
    hgemm_kernel<0,1><<<dim3(1024/TBN, MTOT/TBM), 128>>>(attn_h, val_h, nullptr, nullptr, av_h, 256, 256, 256, 1024);
    // av @ ow + ob -> ao fp32
    hgemm_kernel<1,0><<<dim3(1024/TBN, MTOT/TBM), 128>>>(av_h, ow_h, ob, ao, nullptr, 1024, 1024, 1024, 1024);

    ln_kernel<<<MTOT, 256>>>(h, ao, n1g, n1b, h1, h1_h);

    // FFN1 (+gelu) -> ffi fp16 only
    hgemm_kernel<2,1><<<dim3(4096/TBN, MTOT/TBM), 128>>>(h1_h, fw1_h, fb1, nullptr, ffi_h, 1024, 1024, 1024, 4096);
    // FFN2 -> ff2 fp32
    hgemm_kernel<1,0><<<dim3(1024/TBN, MTOT/TBM), 128>>>(ffi_h, fw2_h, fb2, ff2, nullptr, 4096, 4096, 4096, 1024);

    ln_kernel<<<MTOT, 256>>>(h1, ff2, n2g, n2b, out, nullptr);
}

// round 16
// speedup vs baseline: 1.6198x; 1.0917x over previous
#include <cuda_runtime.h>
#include <cuda_fp16.h>
#include <math.h>
#include <stdint.h>

// Problem constants
#define BB   4
#define NTOK 4096
#define DM   1024
#define DH   256
#define SM_  256
#define HIDN 32
#define MTOT (BB*NTOK)   // 16384

// ---------------- fp32 scratch ----------------
__device__ float g_ctx[BB*DM];
__device__ float g_gamma[BB];
__device__ float g_p[MTOT];
__device__ float g_ppc[(size_t)MTOT*512];     // [pr | pi] (pre-normalize)
__device__ float g_reim[(size_t)MTOT*512];    // [re | im]
__device__ float g_ao[(size_t)MTOT*1024];
__device__ float g_h1[(size_t)MTOT*1024];
__device__ float g_ff2[(size_t)MTOT*1024];
__device__ float g_bcat_b[512];               // [br | bi]
// ---------------- fp16 GEMM operands ----------------
__device__ __half g_h_h[(size_t)MTOT*1024];
__device__ __half g_ppc_h[(size_t)MTOT*512];
__device__ __half g_attn_h[(size_t)MTOT*256];
__device__ __half g_av_h[(size_t)MTOT*1024];
__device__ __half g_h1_h[(size_t)MTOT*1024];
__device__ __half g_ffi_h[(size_t)MTOT*4096];
__device__ __half g_BcatT_h[512*512];         // [n][k]
__device__ __half g_wcat_h[512*1024];         // rows 0..255 Wr^T, 256..511 Wi^T
__device__ __half g_val_h[1024*256];
__device__ __half g_ow_h[1024*1024];
__device__ __half g_fw1_h[(size_t)4096*1024];
__device__ __half g_fw2_h[(size_t)1024*4096];

__device__ __forceinline__ float warp_sum(float v) {
#pragma unroll
    for (int o = 16; o > 0; o >>= 1) v += __shfl_xor_sync(0xffffffffu, v, o);
    return v;
}
__device__ __forceinline__ float gelu_exact(float x) {
    return 0.5f * x * (1.0f + erff(x * 0.70710678118654752440f));
}

// ---------------- fp32 -> fp16 convert ----------------
__global__ void f2h_kernel(const float* __restrict__ in, __half* __restrict__ out, size_t n) {
    size_t i = ((size_t)blockIdx.x * blockDim.x + threadIdx.x) * 4;
    if (i < n) {
        float4 v = *(const float4*)(in + i);
        __half2* o = (__half2*)(out + i);
        o[0] = __floats2half2_rn(v.x, v.y);
        o[1] = __floats2half2_rn(v.z, v.w);
    }
}

// ---------------- transpose to fp16: in[R][C] -> out[C][R] ----------------
__global__ void transpose_h_kernel(const float* __restrict__ in, __half* __restrict__ out,
                                   int R, int C) {
    __shared__ float t[32][33];
    int c0 = blockIdx.x * 32, r0 = blockIdx.y * 32;
    int x = threadIdx.x, y = threadIdx.y;  // 32x8
#pragma unroll
    for (int i = 0; i < 32; i += 8)
        t[y + i][x] = in[(size_t)(r0 + y + i) * C + c0 + x];
    __syncthreads();
#pragma unroll
    for (int i = 0; i < 32; i += 8)
        out[(size_t)(c0 + y + i) * R + r0 + x] = __float2half(t[x][y + i]);
}

// ---------------- ctx = mean over N ----------------
__global__ void ctx_kernel(const float* __restrict__ h) {
    int d = blockIdx.x * blockDim.x + threadIdx.x;
    int b = blockIdx.y;
    const float* hp = h + ((size_t)b * NTOK) * DM + d;
    float s = 0.f;
    for (int n = 0; n < NTOK; n++) s += hp[(size_t)n * DM];
    g_ctx[b * DM + d] = s * (1.0f / NTOK);
}

// ---------------- gamma gate ----------------
__global__ void gamma_kernel(const float* __restrict__ gw1, const float* __restrict__ gb1,
                             const float* __restrict__ gg,  const float* __restrict__ gbeta,
                             const float* __restrict__ gw2, const float* __restrict__ gb2) {
    int b = blockIdx.x;
    int j = threadIdx.x;
    const float* c = g_ctx + b * DM;
    float t = gb1[j];
    for (int k = 0; k < DM; k++) t += c[k] * gw1[k * HIDN + j];
    float mu  = warp_sum(t) * (1.f / 32.f);
    float dv  = t - mu;
    float var = warp_sum(dv * dv) * (1.f / 32.f);
    float tn  = dv * rsqrtf(var + 1e-5f) * gg[j] + gbeta[j];
    float s   = tn / (1.f + expf(-tn));
    float z   = warp_sum(s * gw2[j]);
    if (j == 0) g_gamma[b] = 1.f / (1.f + expf(-(z + gb2[0])));
}

// ---------------- normalize memory + build BcatT (fp16, [n][k]) ----------------
__global__ void mem_kernel(const float* __restrict__ m_real, const float* __restrict__ m_imag) {
    int s = blockIdx.x;
    int k = threadIdx.x;
    float mr = m_real[s * DH + k];
    float mi = m_imag[s * DH + k];
    __shared__ float red[256];
    red[k] = mr * mr + mi * mi;
    __syncthreads();
    for (int o = 128; o > 0; o >>= 1) { if (k < o) red[k] += red[k + o]; __syncthreads(); }
    __shared__ float sc;
    if (k == 0) sc = 1.f / fmaxf(sqrtf(red[0]), 1e-12f);
    __syncthreads();
    float a = mr * sc, b = mi * sc;
    g_BcatT_h[s * 512 + k]               = __float2half(a);
    g_BcatT_h[s * 512 + 256 + k]         = __float2half(b);
    g_BcatT_h[(256 + s) * 512 + k]       = __float2half(b);
    g_BcatT_h[(256 + s) * 512 + 256 + k] = __float2half(-a);
}

// ---------------- bias concat ----------------
__global__ void biascat_kernel(const float* __restrict__ br, const float* __restrict__ bi) {
    int i = threadIdx.x;
    g_bcat_b[i] = (i < 256) ? br[i] : bi[i - 256];
}

// ---------------- per-token: normalize psi (fp16 out), gate, p ----------------
__global__ void rownorm_gate_kernel(const float* __restrict__ h,
    const float* __restrict__ uw1, const float* __restrict__ ub1,
    const float* __restrict__ ug,  const float* __restrict__ ubeta,
    const float* __restrict__ uw2, const float* __restrict__ ub2) {
    int m = blockIdx.x;
    int tid = threadIdx.x;
    float* row = g_ppc + (size_t)m * 512;
    __half* rowh = g_ppc_h + (size_t)m * 512;
    float v0 = row[tid], v1 = row[256 + tid];
    __shared__ float red[256];
    red[tid] = v0 * v0 + v1 * v1;
    __syncthreads();
    for (int o = 128; o > 0; o >>= 1) { if (tid < o) red[tid] += red[tid + o]; __syncthreads(); }
    __shared__ float sc;
    if (tid == 0) sc = 1.f / fmaxf(sqrtf(red[0]), 1e-12f);
    __syncthreads();
    rowh[tid] = __float2half(v0 * sc);
    rowh[256 + tid] = __float2half(v1 * sc);

    int j = tid & 31, part = tid >> 5;
    const float* hr = h + (size_t)m * DM;
    float partial = 0.f;
    int k0 = part * 128;
    for (int k = k0; k < k0 + 128; k++) partial += hr[k] * uw1[k * HIDN + j];
    __shared__ float gred[8][32];
    gred[part][j] = partial;
    __syncthreads();
    if (tid < 32) {
        float t = ub1[tid];
#pragma unroll
        for (int q = 0; q < 8; q++) t += gred[q][tid];
        float mu  = warp_sum(t) * (1.f / 32.f);
        float dv  = t - mu;
        float var = warp_sum(dv * dv) * (1.f / 32.f);
        float tn  = dv * rsqrtf(var + 1e-5f) * ug[tid] + ubeta[tid];
        float s   = tn / (1.f + expf(-tn));
        float z   = warp_sum(s * uw2[tid]);
        if (tid == 0) {
            float pin = 0.95f / (1.f + expf(-(z + ub2[0])));
            g_p[m] = pin * (1.f - g_gamma[m >> 12]);
        }
    }
}

// ---------------- attention row normalize (fp16 out) ----------------
__global__ void attn_kernel() {
    int m = blockIdx.x;
    int s = threadIdx.x;
    float re = g_reim[(size_t)m * 512 + s];
    float im = g_reim[(size_t)m * 512 + 256 + s];
    float pm = g_p[m];
    float raw = (1.f - pm) * (re * re + im * im) + pm * (1.f / 256.f);
    __shared__ float red[256];
    red[s] = raw;
    __syncthreads();
    for (int o = 128; o > 0; o >>= 1) { if (s < o) red[s] += red[s + o]; __syncthreads(); }
    g_attn_h[(size_t)m * 256 + s] = __float2half(raw / (red[0] + 1e-8f));
}

// ---------------- LayerNorm(x + y), optional fp16 secondary output ----------------
__global__ void ln_kernel(const float* __restrict__ x, const float* __restrict__ y,
                          const float* __restrict__ g, const float* __restrict__ bta,
                          float* __restrict__ out, __half* __restrict__ outh) {
    int m = blockIdx.x;
    int tid = threadIdx.x;
    size_t base = (size_t)m * DM;
    float v[4];
    float s1 = 0.f, s2 = 0.f;
#pragma unroll
    for (int i = 0; i < 4; i++) {
        int d = tid + 256 * i;
        v[i] = x[base + d] + y[base + d];
        s1 += v[i];
        s2 += v[i] * v[i];
    }
    __shared__ float r1[256], r2[256];
    r1[tid] = s1; r2[tid] = s2;
    __syncthreads();
    for (int o = 128; o > 0; o >>= 1) {
        if (tid < o) { r1[tid] += r1[tid + o]; r2[tid] += r2[tid + o]; }
        __syncthreads();
    }
    float mu  = r1[0] * (1.f / 1024.f);
    float var = r2[0] * (1.f / 1024.f) - mu * mu;
    float inv = rsqrtf(var + 1e-5f);
#pragma unroll
    for (int i = 0; i < 4; i++) {
        int d = tid + 256 * i;
        float o = (v[i] - mu) * inv * g[d] + bta[d];
        out[base + d] = o;
        if (outh) outh[base + d] = __float2half(o);
    }
}

// ================= fp16 m16n8k16 GEMM with ldmatrix fragments =================
// C[M,N] = A[M,K] @ Bt[N,K]^T (+bias, +gelu). A,Bt fp16 row-major.
// 128 threads, 4 warps, warp tile 64x64, CTA 128x128, TBK=32 halves,
// double-buffered cp.async, ldmatrix.x4 fragment loads (conflict-free, stride 20).
#define TBM 128
#define TBN 128
#define TBKH 32
#define STR 20

__device__ __forceinline__ void cp_async16(void* sdst, const void* gsrc) {
    unsigned s = (unsigned)__cvta_generic_to_shared(sdst);
    asm volatile("cp.async.cg.shared.global [%0], [%1], 16;\n" :: "r"(s), "l"(gsrc));
}
__device__ __forceinline__ void cp_commit() { asm volatile("cp.async.commit_group;\n"); }
__device__ __forceinline__ void cp_wait1()  { asm volatile("cp.async.wait_group 1;\n"); }
__device__ __forceinline__ void cp_wait0()  { asm volatile("cp.async.wait_group 0;\n"); }

__device__ __forceinline__ void ldsm4(uint32_t& r0, uint32_t& r1, uint32_t& r2, uint32_t& r3,
                                      uint32_t saddr) {
    asm volatile("ldmatrix.sync.aligned.m8n8.x4.shared.b16 {%0,%1,%2,%3}, [%4];"
                 : "=r"(r0), "=r"(r1), "=r"(r2), "=r"(r3) : "r"(saddr));
}
__device__ __forceinline__ void mma_f16(float* d, const uint32_t* a, const uint32_t* b) {
    asm volatile(
        "mma.sync.aligned.m16n8k16.row.col.f32.f16.f16.f32 "
        "{%0,%1,%2,%3}, {%4,%5,%6,%7}, {%8,%9}, {%0,%1,%2,%3};"
        : "+f"(d[0]), "+f"(d[1]), "+f"(d[2]), "+f"(d[3])
        : "r"(a[0]), "r"(a[1]), "r"(a[2]), "r"(a[3]), "r"(b[0]), "r"(b[1]));
}

template <int EPI, int OUTH>  // EPI 0:none 1:+bias 2:+bias+gelu; OUTH 0:fp32 1:fp16
__global__ __launch_bounds__(128) void hgemm_kernel(
    const __half* __restrict__ A, const __half* __restrict__ Bt,
    const float* __restrict__ bias, float* __restrict__ Cf, __half* __restrict__ Ch,
    int K, int lda, int ldb, int ldc) {
    __shared__ uint32_t As[2][TBM * STR];
    __shared__ uint32_t Bs[2][TBM * STR];

    int tid  = threadIdx.x;
    int warp = tid >> 5, lane = tid & 31;
    int g = lane >> 2, tg = lane & 3;
    int wm = warp >> 1, wn = warp & 1;
    int row0 = blockIdx.y * TBM, col0 = blockIdx.x * TBN;

    const __half* Ap = A + (size_t)row0 * lda;
    const __half* Bp = Bt + (size_t)col0 * ldb;

    // ldmatrix lane-address offsets (u32 units), loop-invariant.
    int l7 = lane & 7;
    uint32_t ofsA[4], ofsB[4];
#pragma unroll
    for (int mi = 0; mi < 4; mi++)
        ofsA[mi] = (uint32_t)((wm * 64 + mi * 16 + l7 + ((lane >> 3) & 1) * 8) * STR
                              + ((lane >> 4) & 1) * 4);
#pragma unroll
    for (int pi = 0; pi < 4; pi++)
        ofsB[pi] = (uint32_t)((wn * 64 + pi * 16 + l7 + ((lane >> 4) & 1) * 8) * STR
                              + ((lane >> 3) & 1) * 4);

    uint32_t abase[2] = { (uint32_t)__cvta_generic_to_shared(As[0]),
                          (uint32_t)__cvta_generic_to_shared(As[1]) };
    uint32_t bbase[2] = { (uint32_t)__cvta_generic_to_shared(Bs[0]),
                          (uint32_t)__cvta_generic_to_shared(Bs[1]) };

    float acc[4][8][4];
#pragma unroll
    for (int mi = 0; mi < 4; mi++)
#pragma unroll
        for (int ni = 0; ni < 8; ni++)
#pragma unroll
            for (int r = 0; r < 4; r++) acc[mi][ni][r] = 0.f;

    int T = K / TBKH;

    auto load = [&](int st, int kc) {
#pragma unroll
        for (int i = 0; i < 4; i++) {
            int c = tid + i * 128; int r = c >> 2, j = c & 3;
            cp_async16(&As[st][r * STR + j * 4], Ap + (size_t)r * lda + kc * TBKH + j * 8);
        }
#pragma unroll
        for (int i = 0; i < 4; i++) {
            int c = tid + i * 128; int r = c >> 2, j = c & 3;
            cp_async16(&Bs[st][r * STR + j * 4], Bp + (size_t)r * ldb + kc * TBKH + j * 8);
        }
        cp_commit();
    };

    load(0, 0);
    for (int t = 0; t < T; t++) {
        if (t + 1 < T) { load((t + 1) & 1, t + 1); cp_wait1(); }
        else           { cp_wait0(); }
        __syncthreads();
        int st = t & 1;
#pragma unroll
        for (int s = 0; s < 2; s++) {          // two k16 steps per tile
            uint32_t s8 = s * 8;
            uint32_t af[4][4], bf[8][2];
#pragma unroll
            for (int mi = 0; mi < 4; mi++)
                ldsm4(af[mi][0], af[mi][1], af[mi][2], af[mi][3],
                      abase[st] + (ofsA[mi] + s8) * 4);
#pragma unroll
            for (int pi = 0; pi < 4; pi++)
                ldsm4(bf[2*pi][0], bf[2*pi][1], bf[2*pi+1][0], bf[2*pi+1][1],
                      bbase[st] + (ofsB[pi] + s8) * 4);
#pragma unroll
            for (int mi = 0; mi < 4; mi++)
#pragma unroll
                for (int ni = 0; ni < 8; ni++)
                    mma_f16(acc[mi][ni], af[mi], bf[ni]);
        }
        __syncthreads();
    }

    // epilogue
#pragma unroll
    for (int mi = 0; mi < 4; mi++) {
        int r0 = row0 + wm * 64 + mi * 16 + g;
        int r1 = r0 + 8;
#pragma unroll
        for (int ni = 0; ni < 8; ni++) {
            int c = col0 + wn * 64 + ni * 8 + 2 * tg;
            float b0 = 0.f, b1 = 0.f;
            if (EPI > 0) { b0 = bias[c]; b1 = bias[c + 1]; }
            float v0 = acc[mi][ni][0] + b0;
            float v1 = acc[mi][ni][1] + b1;
            float v2 = acc[mi][ni][2] + b0;
            float v3 = acc[mi][ni][3] + b1;
            if (EPI == 2) {
                v0 = gelu_exact(v0); v1 = gelu_exact(v1);
                v2 = gelu_exact(v2); v3 = gelu_exact(v3);
            }
            if (OUTH) {
                *(__half2*)(Ch + (size_t)r0 * ldc + c) = __floats2half2_rn(v0, v1);
                *(__half2*)(Ch + (size_t)r1 * ldc + c) = __floats2half2_rn(v2, v3);
            } else {
                *(float2*)(Cf + (size_t)r0 * ldc + c) = make_float2(v0, v1);
                *(float2*)(Cf + (size_t)r1 * ldc + c) = make_float2(v2, v3);
            }
        }
    }
}

// ---------------- launch ----------------
extern "C" void kernel_launch(void* const* d_in, const int* in_sizes, int n_in,
                              void* d_out, int out_size) {
    const float* h      = (const float*)d_in[0];
    const float* Wr     = (const float*)d_in[1];
    const float* br     = (const float*)d_in[2];
    const float* Wi     = (const float*)d_in[3];
    const float* bi     = (const float*)d_in[4];
    const float* uw1    = (const float*)d_in[5];
    const float* ub1    = (const float*)d_in[6];
    const float* ug     = (const float*)d_in[7];
    const float* ubeta  = (const float*)d_in[8];
    const float* uw2    = (const float*)d_in[9];
    const float* ub2    = (const float*)d_in[10];
    const float* gw1    = (const float*)d_in[11];
    const float* gb1    = (const float*)d_in[12];
    const float* gg     = (const float*)d_in[13];
    const float* gbeta  = (const float*)d_in[14];
    const float* gw2    = (const float*)d_in[15];
    const float* gb2    = (const float*)d_in[16];
    const float* m_real = (const float*)d_in[17];
    const float* m_imag = (const float*)d_in[18];
    const float* values = (const float*)d_in[19];
    const float* ow     = (const float*)d_in[20];
    const float* ob     = (const float*)d_in[21];
    const float* n1g    = (const float*)d_in[22];
    const float* n1b    = (const float*)d_in[23];
    const float* n2g    = (const float*)d_in[24];
    const float* n2b    = (const float*)d_in[25];
    const float* fw1    = (const float*)d_in[26];
    const float* fb1    = (const float*)d_in[27];
    const float* fw2    = (const float*)d_in[28];
    const float* fb2    = (const float*)d_in[29];
    float* out = (float*)d_out;

    float *ppc, *reim, *ao, *h1, *ff2, *bcat_b;
    __half *h_h, *ppc_h, *attn_h, *av_h, *h1_h, *ffi_h;
    __half *BcatT_h, *wcat_h, *val_h, *ow_h, *fw1_h, *fw2_h;
    cudaGetSymbolAddress((void**)&ppc,     g_ppc);
    cudaGetSymbolAddress((void**)&reim,    g_reim);
    cudaGetSymbolAddress((void**)&ao,      g_ao);
    cudaGetSymbolAddress((void**)&h1,      g_h1);
    cudaGetSymbolAddress((void**)&ff2,     g_ff2);
    cudaGetSymbolAddress((void**)&bcat_b,  g_bcat_b);
    cudaGetSymbolAddress((void**)&h_h,     g_h_h);
    cudaGetSymbolAddress((void**)&ppc_h,   g_ppc_h);
    cudaGetSymbolAddress((void**)&attn_h,  g_attn_h);
    cudaGetSymbolAddress((void**)&av_h,    g_av_h);
    cudaGetSymbolAddress((void**)&h1_h,    g_h1_h);
    cudaGetSymbolAddress((void**)&ffi_h,   g_ffi_h);
    cudaGetSymbolAddress((void**)&BcatT_h, g_BcatT_h);
    cudaGetSymbolAddress((void**)&wcat_h,  g_wcat_h);
    cudaGetSymbolAddress((void**)&val_h,   g_val_h);
    cudaGetSymbolAddress((void**)&ow_h,    g_ow_h);
    cudaGetSymbolAddress((void**)&fw1_h,   g_fw1_h);
    cudaGetSymbolAddress((void**)&fw2_h,   g_fw2_h);

    dim3 tb(32, 8);
    transpose_h_kernel<<<dim3(256/32, 1024/32), tb>>>(Wr, wcat_h,            1024, 256);
    transpose_h_kernel<<<dim3(256/32, 1024/32), tb>>>(Wi, wcat_h + 256*1024, 1024, 256);
    transpose_h_kernel<<<dim3(1024/32, 256/32), tb>>>(values, val_h,         256, 1024);
    transpose_h_kernel<<<dim3(1024/32, 1024/32), tb>>>(ow, ow_h,             1024, 1024);
    transpose_h_kernel<<<dim3(4096/32, 1024/32), tb>>>(fw1, fw1_h,           1024, 4096);
    transpose_h_kernel<<<dim3(1024/32, 4096/32), tb>>>(fw2, fw2_h,           4096, 1024);
    biascat_kernel<<<1, 512>>>(br, bi);

    f2h_kernel<<<((size_t)MTOT*1024/4 + 255)/256, 256>>>(h, h_h, (size_t)MTOT*1024);

    ctx_kernel<<<dim3(DM / 256, BB), 256>>>(h);
    gamma_kernel<<<BB, 32>>>(gw1, gb1, gg, gbeta, gw2, gb2);
    mem_kernel<<<SM_, 256>>>(m_real, m_imag);

    // encoder (fused Wr|Wi): ppc[M,512] fp32 = h_h @ wcat_h^T + bcat
    hgemm_kernel<1,0><<<dim3(512/TBN, MTOT/TBM), 128>>>(h_h, wcat_h, bcat_b, ppc, nullptr, 1024, 1024, 1024, 512);

    rownorm_gate_kernel<<<MTOT, 256>>>(h, uw1, ub1, ug, ubeta, uw2, ub2);

    // overlap: reim fp32 = ppc_h @ BcatT_h^T
    hgemm_kernel<0,0><<<dim3(512/TBN, MTOT/TBM), 128>>>(ppc_h, BcatT_h, nullptr, reim, nullptr, 512, 512, 512, 512);

    attn_kernel<<<MTOT, 256>>>();

    hgemm_kernel<0,1><<<dim3(1024/TBN, MTOT/TBM), 128>>>(attn_h, val_h, nullptr, nullptr, av_h, 256, 256, 256, 1024);
    hgemm_kernel<1,0><<<dim3(1024/TBN, MTOT/TBM), 128>>>(av_h, ow_h, ob, ao, nullptr, 1024, 1024, 1024, 1024);

    ln_kernel<<<MTOT, 256>>>(h, ao, n1g, n1b, h1, h1_h);

    hgemm_kernel<2,1><<<dim3(4096/TBN, MTOT/TBM), 128>>>(h1_h, fw1_h, fb1, nullptr, ffi_h, 1024, 1024, 1024, 4096);
    hgemm_kernel<1,0><<<dim3(1024/TBN, MTOT/TBM), 128>>>(ffi_h, fw2_h, fb2, ff2, nullptr, 4096, 4096, 4096, 1024);

    ln_kernel<<<MTOT, 256>>>(h1, ff2, n2g, n2b, out, nullptr);
}